// round 15
// baseline (speedup 1.0000x reference)
#include <cuda_runtime.h>

// EMA scan: out[b,t,d] = a*out[b,t-1,d] + (1-a)*x[b,t,d], out[b,-1,d]=0
// Shapes fixed: B=4, S=4096, D=2048, fp32.
//
// Single kernel, CTA owns 32 channels (16 packed float2 lanes) for the
// whole sequence: x read once, out written once (268MB traffic floor).
// f32x2 packed math + 64-bit memory ops (r13) at 32 warps/SM (r12's
// proven occupancy): TPB = 512 = 16 lanes x 32 sub-chunks of LEN=8.
// 16 stages of 256 steps, 1 barrier/stage, parity-buffered smem,
// x2 ping-pong register prefetch. 256 CTAs, 2 CTAs/SM.

#define B 4
#define S 4096
#define D 2048
#define D2 (D / 2)             // 1024 float2 columns
#define LANES 16               // float2 lanes per CTA (= 32 channels)
#define SC 32                  // sub-chunks per stage
#define LEN 8                  // timesteps per sub-chunk
#define STAGE_T (SC * LEN)     // 256
#define NSTAGE (S / STAGE_T)   // 16 (even: required by the x2 unroll)
#define TPB (LANES * SC)       // 512

typedef unsigned long long u64;

__host__ __device__ constexpr float pow_alpha(int n) {
    double r = 1.0;
    for (int i = 0; i < n; ++i) r *= 0.99;
    return (float)r;
}

// Pack one float into both f32x2 lanes (compile-time).
__host__ __device__ constexpr u64 packf2(float v) {
    unsigned u = __builtin_bit_cast(unsigned, v);
    return (u64)u | ((u64)u << 32);
}

// DECP2[i] = alpha^(LEN*i) packed into both lanes, i = 0..SC-1.
__constant__ u64 DECP2[SC] = {
    packf2(pow_alpha(0)),   packf2(pow_alpha(8)),
    packf2(pow_alpha(16)),  packf2(pow_alpha(24)),
    packf2(pow_alpha(32)),  packf2(pow_alpha(40)),
    packf2(pow_alpha(48)),  packf2(pow_alpha(56)),
    packf2(pow_alpha(64)),  packf2(pow_alpha(72)),
    packf2(pow_alpha(80)),  packf2(pow_alpha(88)),
    packf2(pow_alpha(96)),  packf2(pow_alpha(104)),
    packf2(pow_alpha(112)), packf2(pow_alpha(120)),
    packf2(pow_alpha(128)), packf2(pow_alpha(136)),
    packf2(pow_alpha(144)), packf2(pow_alpha(152)),
    packf2(pow_alpha(160)), packf2(pow_alpha(168)),
    packf2(pow_alpha(176)), packf2(pow_alpha(184)),
    packf2(pow_alpha(192)), packf2(pow_alpha(200)),
    packf2(pow_alpha(208)), packf2(pow_alpha(216)),
    packf2(pow_alpha(224)), packf2(pow_alpha(232)),
    packf2(pow_alpha(240)), packf2(pow_alpha(248))
};

__device__ __forceinline__ u64 fma2(u64 a, u64 b, u64 c) {
    u64 r;
    asm("fma.rn.f32x2 %0, %1, %2, %3;" : "=l"(r) : "l"(a), "l"(b), "l"(c));
    return r;
}
__device__ __forceinline__ u64 mul2(u64 a, u64 b) {
    u64 r;
    asm("mul.rn.f32x2 %0, %1, %2;" : "=l"(r) : "l"(a), "l"(b));
    return r;
}

// One stage: prefetch next tile (pre-scaled by om) into WNXT, scan WCUR,
// exchange carries (compile-time parity P), rescan + store.
#define STAGE_BODY(P, WCUR, WNXT, xn, op, do_pf)                           \
    {                                                                      \
        if (do_pf) {                                                       \
            _Pragma("unroll")                                              \
            for (int j = 0; j < LEN; ++j)                                  \
                WNXT[j] = mul2(OM2, __ldcs(&(xn)[(size_t)j * D2]));        \
        }                                                                  \
        u64 e = 0ull;                                                      \
        _Pragma("unroll")                                                  \
        for (int j = 0; j < LEN; ++j) e = fma2(A2, e, WCUR[j]);            \
        s_ends[P][sc][ch] = e;                                             \
        __syncthreads();                                                   \
        u64 carry = mul2(DECP2[sc], s_carry[P][ch]);                       \
        _Pragma("unroll")                                                  \
        for (int i = 0; i < SC - 1; ++i) {                                 \
            const u64 ei = s_ends[P][i][ch];                               \
            const int idx = sc - 1 - i;                                    \
            const u64 w = (idx >= 0) ? DECP2[idx] : 0ull;                  \
            carry = fma2(w, ei, carry);                                    \
        }                                                                  \
        if (sc == SC - 1)                                                  \
            s_carry[(P) ^ 1][ch] = fma2(DECP2[1], carry, e);               \
        u64 ema = carry;                                                   \
        _Pragma("unroll")                                                  \
        for (int j = 0; j < LEN; ++j) {                                    \
            ema = fma2(A2, ema, WCUR[j]);                                  \
            __stcs(&(op)[(size_t)j * D2], ema);                            \
        }                                                                  \
    }

__global__ void __launch_bounds__(TPB, 2)
ema_cta(const u64* __restrict__ x, u64* __restrict__ out) {
    __shared__ u64 s_ends[2][SC][LANES];   // parity-buffered sub-chunk ends
    __shared__ u64 s_carry[2][LANES];      // parity-buffered stage carry

    const int tid = threadIdx.x;
    const int ch = tid & (LANES - 1);      // float2 lane within CTA
    const int sc = tid >> 4;               // sub-chunk id (0..31)
    const int d2 = blockIdx.x * LANES + ch;
    const int b = blockIdx.y;

    constexpr u64 A2  = packf2(0.99f);
    constexpr u64 OM2 = packf2(0.01f);

    if (tid < LANES) s_carry[0][tid] = 0ull;   // ordered by stage-0 barrier

    // This thread's sub-chunk column base (stage 0); advance by constant.
    const size_t col = (size_t)b * S * D2 + (size_t)sc * LEN * D2 + d2;
    const u64* xp = x + col;
    u64* op = out + col;
    const size_t STRIDE = (size_t)STAGE_T * D2;

    u64 w0[LEN], w1[LEN];
#pragma unroll
    for (int j = 0; j < LEN; ++j)
        w0[j] = mul2(OM2, __ldcs(&xp[(size_t)j * D2]));

#pragma unroll 1
    for (int st = 0; st < NSTAGE; st += 2) {
        // Stage st (parity 0): consume w0, prefetch w1.
        STAGE_BODY(0, w0, w1, xp + STRIDE, op, true)
        xp += STRIDE; op += STRIDE;

        // Stage st+1 (parity 1): consume w1, prefetch w0 (skip on last).
        const bool pf = (st + 2 < NSTAGE);
        STAGE_BODY(1, w1, w0, xp + STRIDE, op, pf)
        xp += STRIDE; op += STRIDE;
    }
}

extern "C" void kernel_launch(void* const* d_in, const int* in_sizes, int n_in,
                              void* d_out, int out_size) {
    const u64* x = (const u64*)d_in[0];
    u64* out = (u64*)d_out;

    dim3 grid(D2 / LANES, B);   // (64, 4) = 256 CTAs
    ema_cta<<<grid, TPB>>>(x, out);
}

// round 16
// speedup vs baseline: 1.2050x; 1.2050x over previous
#include <cuda_runtime.h>

// EMA scan: out[b,t,d] = a*out[b,t-1,d] + (1-a)*x[b,t,d], out[b,-1,d]=0
// Shapes fixed: B=4, S=4096, D=2048, fp32.
//
// Single kernel, CTA owns 32 channels for the whole sequence (traffic
// floor: x read once, out written once = 268MB). Round-16 vs round-12
// (the best kernel, 45.6us): algebraic restructure using
//   ema_j = carry * alpha^(j+1) + local_j
//  - local scan keeps its prefix IN the v registers (one MUL+FMA/step)
//  - the seeded rescan becomes 16 INDEPENDENT fma(carry, PW[j], v[j])
//    (no serial chain after the barrier; one fewer MUL/step overall)
//  - carry weighted-sum split into 2 accumulators (serial depth 15 -> 8)
// Same shape as r12: CTA = 512 thr = 32 ch x 16 sub-chunks of LEN=16;
// 16 stages, 1 barrier/stage, parity-buffered smem, x2 ping-pong
// prefetch, __ldcs/__stcs. 256 CTAs, 2 CTAs/SM.

#define B 4
#define S 4096
#define D 2048
#define CH 32                  // channels per CTA
#define SC 16                  // sub-chunks per stage (== warps)
#define LEN 16                 // timesteps per sub-chunk
#define STAGE_T (SC * LEN)     // 256
#define NSTAGE (S / STAGE_T)   // 16 (even: required by the x2 unroll)
#define TPB (CH * SC)          // 512

constexpr float ALPHA = 0.99f;
constexpr float ONEM  = 0.01f;

__host__ __device__ constexpr float pow_alpha(int n) {
    double r = 1.0;
    for (int i = 0; i < n; ++i) r *= 0.99;
    return (float)r;
}

// DECP[i] = alpha^(LEN*i)
__constant__ float DECP[SC] = {
    pow_alpha(0),   pow_alpha(16),  pow_alpha(32),  pow_alpha(48),
    pow_alpha(64),  pow_alpha(80),  pow_alpha(96),  pow_alpha(112),
    pow_alpha(128), pow_alpha(144), pow_alpha(160), pow_alpha(176),
    pow_alpha(192), pow_alpha(208), pow_alpha(224), pow_alpha(240)
};

// PW[j] = alpha^(j+1): weight of the incoming carry at step j.
__constant__ float PW[LEN] = {
    pow_alpha(1),  pow_alpha(2),  pow_alpha(3),  pow_alpha(4),
    pow_alpha(5),  pow_alpha(6),  pow_alpha(7),  pow_alpha(8),
    pow_alpha(9),  pow_alpha(10), pow_alpha(11), pow_alpha(12),
    pow_alpha(13), pow_alpha(14), pow_alpha(15), pow_alpha(16)
};

// One stage: prefetch next tile into VN, local scan (prefix kept in V),
// exchange carries (compile-time parity P), independent correction+store.
#define STAGE_BODY(P, V, VN, xn, op, do_pf)                                \
    {                                                                      \
        if (do_pf) {                                                       \
            _Pragma("unroll")                                              \
            for (int j = 0; j < LEN; ++j)                                  \
                VN[j] = __ldcs(&(xn)[(size_t)j * D]);                      \
        }                                                                  \
        float e = 0.0f;                                                    \
        _Pragma("unroll")                                                  \
        for (int j = 0; j < LEN; ++j) {                                    \
            e = fmaf(ALPHA, e, ONEM * V[j]);                               \
            V[j] = e;         /* keep local prefix */                      \
        }                                                                  \
        s_ends[P][sc][ch] = e;                                             \
        __syncthreads();                                                   \
        float acc0 = DECP[sc] * s_carry[P][ch];                            \
        float acc1 = 0.0f;                                                 \
        _Pragma("unroll")                                                  \
        for (int i = 0; i < SC - 1; i += 2) {                              \
            const int i0 = sc - 1 - i;                                     \
            const float w0 = (i0 >= 0) ? DECP[i0] : 0.0f;                  \
            acc0 = fmaf(w0, s_ends[P][i][ch], acc0);                       \
            if (i + 1 < SC - 1) {                                          \
                const int i1 = sc - 2 - i;                                 \
                const float w1 = (i1 >= 0) ? DECP[i1] : 0.0f;              \
                acc1 = fmaf(w1, s_ends[P][i + 1][ch], acc1);               \
            }                                                              \
        }                                                                  \
        const float carry = acc0 + acc1;                                   \
        if (sc == SC - 1)                                                  \
            s_carry[(P) ^ 1][ch] = fmaf(DECP[1], carry, e);                \
        _Pragma("unroll")                                                  \
        for (int j = 0; j < LEN; ++j)                                      \
            __stcs(&(op)[(size_t)j * D], fmaf(carry, PW[j], V[j]));        \
    }

__global__ void __launch_bounds__(TPB, 2)
ema_cta(const float* __restrict__ x, float* __restrict__ out) {
    __shared__ float s_ends[2][SC][CH];   // parity-buffered sub-chunk ends
    __shared__ float s_carry[2][CH];      // parity-buffered stage carry

    const int tid = threadIdx.x;
    const int ch = tid & (CH - 1);
    const int sc = tid >> 5;              // warp id == sub-chunk id (uniform)
    const int d = blockIdx.x * CH + ch;
    const int b = blockIdx.y;

    if (tid < CH) s_carry[0][tid] = 0.0f;   // ordered by stage-0 barrier

    // This thread's sub-chunk column base (stage 0); advance by constant.
    const size_t col = (size_t)b * S * D + (size_t)sc * LEN * D + d;
    const float* xp = x + col;
    float* op = out + col;
    const size_t STRIDE = (size_t)STAGE_T * D;

    float v0[LEN], v1[LEN];
#pragma unroll
    for (int j = 0; j < LEN; ++j) v0[j] = __ldcs(&xp[(size_t)j * D]);

#pragma unroll 1
    for (int st = 0; st < NSTAGE; st += 2) {
        // Stage st (parity 0): consume v0, prefetch v1.
        STAGE_BODY(0, v0, v1, xp + STRIDE, op, true)
        xp += STRIDE; op += STRIDE;

        // Stage st+1 (parity 1): consume v1, prefetch v0 (skip on last).
        const bool pf = (st + 2 < NSTAGE);
        STAGE_BODY(1, v1, v0, xp + STRIDE, op, pf)
        xp += STRIDE; op += STRIDE;
    }
}

extern "C" void kernel_launch(void* const* d_in, const int* in_sizes, int n_in,
                              void* d_out, int out_size) {
    const float* x = (const float*)d_in[0];
    float* out = (float*)d_out;

    dim3 grid(D / CH, B);   // (64, 4) = 256 CTAs
    ema_cta<<<grid, TPB>>>(x, out);
}